// round 11
// baseline (speedup 1.0000x reference)
#include <cuda_runtime.h>

// WidthAP: out[b,0,i,h] = sum_{j=0..4} x[b,0,i+j,h] * attn[b,i+j]
// x: (32,1,2052,768) fp32, attn: (32,2052) fp32, out: (32,1,2048,768) fp32.
//
// Register-ring kernel (R3/R4 codegen shape: 8-deep front-batched LDG.128
// bursts, 64 regs, static smem -> low graph-replay overhead) with one-wave
// tiling: 9 tiles/batch = 288 CTAs, tiles 4x232 + 5x224 rows, halo 1.76%.

#define LENGTH   2048
#define WIDTH    5
#define PADDED   (LENGTH + WIDTH - 1)   // 2052
#define BATCH    32
#define HDIM     768
#define H4       (HDIM / 4)             // 192 float4 lanes
#define TPB      9                      // tiles per batch -> 288 CTAs (one wave)
#define BIGT     4                      // tiles 0..3: 232 rows; 4..8: 224 rows
#define UB       8                      // front-batched load burst depth
#define WMAX     236                    // max weights per tile (232 + 4)

__device__ __forceinline__ float4 f4_scale(float4 v, float s) {
    return make_float4(v.x * s, v.y * s, v.z * s, v.w * s);
}
__device__ __forceinline__ float4 f4_add(float4 a, float4 b) {
    return make_float4(a.x + b.x, a.y + b.y, a.z + b.z, a.w + b.w);
}

__global__ __launch_bounds__(H4) void widthap_kernel(
    const float4* __restrict__ x,      // (B, PADDED, H4)
    const float*  __restrict__ attn,   // (B, PADDED)
    float4*       __restrict__ out)    // (B, LENGTH, H4)
{
    const int lane = threadIdx.x;          // 0..191, one float4 column
    const int tile = blockIdx.x;           // 0..8
    const int b    = blockIdx.y;           // 0..31

    // Tile geometry: tiles 0..3 -> 232 rows, tiles 4..8 -> 224 rows.
    const int i0    = (tile < BIGT) ? tile * 232 : BIGT * 232 + (tile - BIGT) * 224;
    const int nrows = (tile < BIGT) ? 232 : 224;

    __shared__ float w[WMAX];
    for (int k = lane; k < nrows + WIDTH - 1; k += H4)
        w[k] = attn[b * PADDED + i0 + k];
    __syncthreads();

    const float4* xp = x   + ((long)b * PADDED + i0) * H4 + lane;
    float4*       op = out + ((long)b * LENGTH + i0) * H4 + lane;

    // Prime the 5-deep weighted window (tile rows 0..3).
    float4 v0 = f4_scale(__ldcs(xp + 0 * H4), w[0]);
    float4 v1 = f4_scale(__ldcs(xp + 1 * H4), w[1]);
    float4 v2 = f4_scale(__ldcs(xp + 2 * H4), w[2]);
    float4 v3 = f4_scale(__ldcs(xp + 3 * H4), w[3]);

    // Last feeding row: nrows-1 + 4 = nrows+3 -> global i0+nrows+3 <= 2051. In-bounds.
    for (int i = 0; i < nrows; i += UB) {
        // Batch of 8 independent streaming loads (front-batched MLP).
        float4 xv[UB];
        #pragma unroll
        for (int u = 0; u < UB; u++)
            xv[u] = __ldcs(xp + (i + 4 + u) * H4);

        // Weighted ring + outputs for 8 rows (o[] buffering protects the
        // load batch from being interleaved by ptxas -- R3-proven shape).
        float4 o[UB];
        #pragma unroll
        for (int u = 0; u < UB; u++) {
            float4 v4 = f4_scale(xv[u], w[i + 4 + u]);
            o[u] = f4_add(f4_add(f4_add(v0, v1), f4_add(v2, v3)), v4);
            v0 = v1; v1 = v2; v2 = v3; v3 = v4;
        }

        #pragma unroll
        for (int u = 0; u < UB; u++)
            __stcs(op + (i + u) * H4, o[u]);
    }
}

extern "C" void kernel_launch(void* const* d_in, const int* in_sizes, int n_in,
                              void* d_out, int out_size)
{
    const float4* x    = (const float4*)d_in[0];
    const float*  attn = (const float*)d_in[1];
    float4*       out  = (float4*)d_out;

    dim3 grid(TPB, BATCH);
    widthap_kernel<<<grid, H4>>>(x, attn, out);
}

// round 12
// speedup vs baseline: 1.0833x; 1.0833x over previous
#include <cuda_runtime.h>

// WidthAP: out[b,0,i,h] = sum_{j=0..4} x[b,0,i+j,h] * attn[b,i+j]
// x: (32,1,2052,768) fp32, attn: (32,2052) fp32, out: (32,1,2048,768) fp32.
//
// R3 shape (proven best on the scored bench): 512 CTAs (ITILE=128),
// 8-deep front-batched LDG.128 bursts protected by o[] buffering, 64 regs,
// tiny static smem. Change vs R3: x loads use default caching (not __ldcs)
// so the 4-row inter-tile halo can hit L2 from the neighbor CTA's stream;
// stores stay __stcs (output has zero reuse).

#define LENGTH   2048
#define WIDTH    5
#define PADDED   (LENGTH + WIDTH - 1)   // 2052
#define BATCH    32
#define HDIM     768
#define H4       (HDIM / 4)             // 192 float4 lanes
#define ITILE    128                    // rows per block -> 512 CTAs
#define NTILES   (LENGTH / ITILE)       // 16
#define UB       8                      // front-batched load burst depth

__device__ __forceinline__ float4 f4_scale(float4 v, float s) {
    return make_float4(v.x * s, v.y * s, v.z * s, v.w * s);
}
__device__ __forceinline__ float4 f4_add(float4 a, float4 b) {
    return make_float4(a.x + b.x, a.y + b.y, a.z + b.z, a.w + b.w);
}

__global__ __launch_bounds__(H4) void widthap_kernel(
    const float4* __restrict__ x,      // (B, PADDED, H4)
    const float*  __restrict__ attn,   // (B, PADDED)
    float4*       __restrict__ out)    // (B, LENGTH, H4)
{
    const int lane = threadIdx.x;          // 0..191, one float4 column
    const int tile = blockIdx.x;           // 0..15
    const int b    = blockIdx.y;           // 0..31
    const int i0   = tile * ITILE;

    __shared__ float w[ITILE + WIDTH - 1]; // 132 weights
    for (int k = lane; k < ITILE + WIDTH - 1; k += H4)
        w[k] = attn[b * PADDED + i0 + k];
    __syncthreads();

    const float4* xp = x   + ((long)b * PADDED + i0) * H4 + lane;
    float4*       op = out + ((long)b * LENGTH + i0) * H4 + lane;

    // Prime the 5-deep weighted window (first 4 rows).
    float4 v0 = f4_scale(__ldg(xp + 0 * H4), w[0]);
    float4 v1 = f4_scale(__ldg(xp + 1 * H4), w[1]);
    float4 v2 = f4_scale(__ldg(xp + 2 * H4), w[2]);
    float4 v3 = f4_scale(__ldg(xp + 3 * H4), w[3]);

    for (int i = 0; i < ITILE; i += UB) {
        // Batch of 8 independent loads (front-batched MLP, default caching).
        float4 xv[UB];
        #pragma unroll
        for (int u = 0; u < UB; u++)
            xv[u] = __ldg(xp + (i + 4 + u) * H4);

        // Weighted ring + outputs for 8 rows (o[] buffering protects the
        // load batch from being interleaved by ptxas).
        float4 o[UB];
        #pragma unroll
        for (int u = 0; u < UB; u++) {
            float4 v4 = f4_scale(xv[u], w[i + 4 + u]);
            o[u] = f4_add(f4_add(f4_add(v0, v1), f4_add(v2, v3)), v4);
            v0 = v1; v1 = v2; v2 = v3; v3 = v4;
        }

        #pragma unroll
        for (int u = 0; u < UB; u++)
            __stcs(op + (i + u) * H4, o[u]);
    }
}

extern "C" void kernel_launch(void* const* d_in, const int* in_sizes, int n_in,
                              void* d_out, int out_size)
{
    const float4* x    = (const float4*)d_in[0];
    const float*  attn = (const float*)d_in[1];
    float4*       out  = (float4*)d_out;

    dim3 grid(NTILES, BATCH);
    widthap_kernel<<<grid, H4>>>(x, attn, out);
}

// round 13
// speedup vs baseline: 1.1396x; 1.0520x over previous
#include <cuda_runtime.h>

// WidthAP: out[b,0,i,h] = sum_{j=0..4} x[b,0,i+j,h] * attn[b,i+j]
// x: (32,1,2052,768) fp32, attn: (32,2052) fp32, out: (32,1,2048,768) fp32.
//
// Converged best configuration (R3): 512 CTAs (ITILE=128), 8-deep
// front-batched __ldcs LDG.128 bursts protected by o[] buffering (keeps
// ptxas from interleaving loads with consumers; 64 regs), __stcs stores,
// tiny static smem. DRAM-bound at the mixed read/write stream ceiling.

#define LENGTH   2048
#define WIDTH    5
#define PADDED   (LENGTH + WIDTH - 1)   // 2052
#define BATCH    32
#define HDIM     768
#define H4       (HDIM / 4)             // 192 float4 lanes
#define ITILE    128                    // rows per block
#define NTILES   (LENGTH / ITILE)       // 16
#define UNROLL   8

__device__ __forceinline__ float4 f4_scale(float4 v, float s) {
    return make_float4(v.x * s, v.y * s, v.z * s, v.w * s);
}
__device__ __forceinline__ float4 f4_add(float4 a, float4 b) {
    return make_float4(a.x + b.x, a.y + b.y, a.z + b.z, a.w + b.w);
}

__global__ __launch_bounds__(H4) void widthap_kernel(
    const float4* __restrict__ x,      // (B, PADDED, H4)
    const float*  __restrict__ attn,   // (B, PADDED)
    float4*       __restrict__ out)    // (B, LENGTH, H4)
{
    const int lane = threadIdx.x;          // 0..191, one float4 column
    const int tile = blockIdx.x;           // 0..15
    const int b    = blockIdx.y;           // 0..31
    const int i0   = tile * ITILE;

    __shared__ float w[ITILE + WIDTH - 1]; // 132 weights
    for (int k = lane; k < ITILE + WIDTH - 1; k += blockDim.x)
        w[k] = attn[b * PADDED + i0 + k];
    __syncthreads();

    const float4* xp = x   + ((long)b * PADDED + i0) * H4 + lane;
    float4*       op = out + ((long)b * LENGTH + i0) * H4 + lane;

    // Prime the 5-deep weighted window (first 4 rows).
    float4 v0 = f4_scale(__ldcs(xp + 0 * H4), w[0]);
    float4 v1 = f4_scale(__ldcs(xp + 1 * H4), w[1]);
    float4 v2 = f4_scale(__ldcs(xp + 2 * H4), w[2]);
    float4 v3 = f4_scale(__ldcs(xp + 3 * H4), w[3]);

    for (int i = 0; i < ITILE; i += UNROLL) {
        // Batch of 8 independent streaming loads (front-batched MLP).
        float4 xv[UNROLL];
        #pragma unroll
        for (int u = 0; u < UNROLL; u++)
            xv[u] = __ldcs(xp + (i + 4 + u) * H4);

        // Weighted ring + outputs for 8 rows.
        float4 o[UNROLL];
        #pragma unroll
        for (int u = 0; u < UNROLL; u++) {
            float4 v4 = f4_scale(xv[u], w[i + 4 + u]);
            o[u] = f4_add(f4_add(f4_add(v0, v1), f4_add(v2, v3)), v4);
            v0 = v1; v1 = v2; v2 = v3; v3 = v4;
        }

        // Batch of 8 streaming stores.
        #pragma unroll
        for (int u = 0; u < UNROLL; u++)
            __stcs(op + (i + u) * H4, o[u]);
    }
}

extern "C" void kernel_launch(void* const* d_in, const int* in_sizes, int n_in,
                              void* d_out, int out_size)
{
    const float4* x    = (const float4*)d_in[0];
    const float*  attn = (const float*)d_in[1];
    float4*       out  = (float4*)d_out;

    dim3 grid(NTILES, BATCH);
    widthap_kernel<<<grid, H4>>>(x, attn, out);
}